// round 4
// baseline (speedup 1.0000x reference)
#include <cuda_runtime.h>
#include <cstdint>

// Problem constants (fixed-shape problem: G=4000, B=8, DEG=32, BATCH=128)
#define G_     4000
#define BSZ    8
#define DEG_   32
#define NB_    (G_ * DEG_ + G_)     // 132000 blocks
#define BATCH_ 128
#define D_     (G_ * BSZ)           // 32000
#define WCH    32                   // w blocks staged in smem per chunk

typedef unsigned long long ull;

// Scratch (no allocations allowed -> __device__ globals)
__device__ int   g_count[G_];
__device__ int   g_off[G_];
__device__ int   g_cur[G_];
__device__ int2  g_entries[NB_];                 // (block id n, src group)
__device__ float g_xT[(size_t)D_ * BATCH_];      // xT[col * 128 + b]

// ---------------- preprocessing: counting sort by block_out ----------------

__global__ void zero_counts() {
    int i = blockIdx.x * blockDim.x + threadIdx.x;
    if (i < G_) g_count[i] = 0;
}

__global__ void hist_kernel(const int* __restrict__ bo) {
    int n = blockIdx.x * blockDim.x + threadIdx.x;
    if (n < NB_) atomicAdd(&g_count[bo[n]], 1);
}

// Single-CTA scan over 4000 bins (1024 threads x 4 bins each)
__global__ void scan_kernel() {
    __shared__ int ssum[1024];
    int t = threadIdx.x;
    int base = t * 4;
    int v[4];
    int s = 0;
#pragma unroll
    for (int k = 0; k < 4; k++) {
        int c = (base + k < G_) ? g_count[base + k] : 0;
        v[k] = s;
        s += c;
    }
    ssum[t] = s;
    __syncthreads();
    for (int off = 1; off < 1024; off <<= 1) {
        int add = (t >= off) ? ssum[t - off] : 0;
        __syncthreads();
        ssum[t] += add;
        __syncthreads();
    }
    int tbase = ssum[t] - s;  // exclusive base for this thread's 4 bins
#pragma unroll
    for (int k = 0; k < 4; k++) {
        if (base + k < G_) {
            int o = tbase + v[k];
            g_off[base + k] = o;
            g_cur[base + k] = o;
        }
    }
}

__global__ void scatter_kernel(const int* __restrict__ bi, const int* __restrict__ bo) {
    int n = blockIdx.x * blockDim.x + threadIdx.x;
    if (n < NB_) {
        int p = atomicAdd(&g_cur[bo[n]], 1);
        g_entries[p] = make_int2(n, bi[n]);
    }
}

// ---------------- transpose x (BATCH, D) -> xT (D, BATCH) ----------------

__global__ void transpose_kernel(const float* __restrict__ x) {
    __shared__ float tile[32][33];
    int c0 = blockIdx.x * 32;  // along D
    int r0 = blockIdx.y * 32;  // along BATCH
    int tx = threadIdx.x, ty = threadIdx.y;  // (32, 8)
#pragma unroll
    for (int r = 0; r < 4; r++)
        tile[ty + 8 * r][tx] = x[(size_t)(r0 + ty + 8 * r) * D_ + (c0 + tx)];
    __syncthreads();
#pragma unroll
    for (int r = 0; r < 4; r++)
        g_xT[(size_t)(c0 + ty + 8 * r) * BATCH_ + (r0 + tx)] = tile[tx][ty + 8 * r];
}

// ---------------- main: per output group, gather + packed-f32x2 GEMM ----------------

__device__ __forceinline__ void ffma2(ull& d, ull a, ull b) {
    // Blackwell packed fp32: two independent FMAs per instruction
    asm("fma.rn.f32x2 %0, %1, %2, %0;" : "+l"(d) : "l"(a), "l"(b));
}
__device__ __forceinline__ ull pack2(float v) {
    unsigned u = __float_as_uint(v);
    return ((ull)u << 32) | (ull)u;
}

__global__ void __launch_bounds__(128) main_kernel(const float* __restrict__ x,
                                                   const float* __restrict__ w,
                                                   float* __restrict__ out) {
    int g = blockIdx.x;        // output group
    int b = threadIdx.x;       // batch column, 0..127
    int start = g_off[g];
    int cnt   = g_count[g];

    __shared__ __align__(16) float sw[WCH][64];  // staged w blocks [j][i*8+o]
    __shared__ int ssrc[WCH];

    // packed accumulators: a0=(o0,o1) a1=(o2,o3) a2=(o4,o5) a3=(o6,o7)
    ull a0 = 0, a1 = 0, a2 = 0, a3 = 0;

    for (int c0 = 0; c0 < cnt; c0 += WCH) {
        int m = cnt - c0;
        if (m > WCH) m = WCH;
        // Cooperative stage of m w-blocks (64 floats each) into smem
        for (int idx = threadIdx.x; idx < m * 64; idx += 128) {
            int j = idx >> 6, f = idx & 63;
            int n = g_entries[start + c0 + j].x;
            sw[j][f] = w[(size_t)n * 64 + f];
        }
        if (threadIdx.x < m) ssrc[threadIdx.x] = g_entries[start + c0 + threadIdx.x].y;
        __syncthreads();

        for (int j = 0; j < m; j++) {
            int src = ssrc[j];
            const float* xp = g_xT + (size_t)src * (BSZ * BATCH_) + b;  // coalesced
            const ull* wp = (const ull*)(&sw[j][0]);                    // broadcast LDS
#pragma unroll
            for (int i = 0; i < 8; i++) {
                ull x2 = pack2(xp[i * BATCH_]);
                ffma2(a0, x2, wp[i * 4 + 0]);
                ffma2(a1, x2, wp[i * 4 + 1]);
                ffma2(a2, x2, wp[i * 4 + 2]);
                ffma2(a3, x2, wp[i * 4 + 3]);
            }
        }
        __syncthreads();
    }

    // Epilogue: residual + store (once per group; scattered but tiny total traffic)
    size_t obase = (size_t)b * D_ + (size_t)g * 8;
    float4 r0 = *(const float4*)(x + obase);
    float4 r1 = *(const float4*)(x + obase + 4);
    float4 o0, o1;
    o0.x = r0.x + __uint_as_float((unsigned)(a0 & 0xffffffffu));
    o0.y = r0.y + __uint_as_float((unsigned)(a0 >> 32));
    o0.z = r0.z + __uint_as_float((unsigned)(a1 & 0xffffffffu));
    o0.w = r0.w + __uint_as_float((unsigned)(a1 >> 32));
    o1.x = r1.x + __uint_as_float((unsigned)(a2 & 0xffffffffu));
    o1.y = r1.y + __uint_as_float((unsigned)(a2 >> 32));
    o1.z = r1.z + __uint_as_float((unsigned)(a3 & 0xffffffffu));
    o1.w = r1.w + __uint_as_float((unsigned)(a3 >> 32));
    *(float4*)(out + obase)     = o0;
    *(float4*)(out + obase + 4) = o1;
}

// ---------------- launch ----------------

extern "C" void kernel_launch(void* const* d_in, const int* in_sizes, int n_in,
                              void* d_out, int out_size) {
    const float* x  = (const float*)d_in[0];   // (128, 32000) f32
    const float* w  = (const float*)d_in[1];   // (132000, 8, 8) f32
    const int*   bi = (const int*)d_in[2];     // block_in
    const int*   bo = (const int*)d_in[3];     // block_out
    float* out = (float*)d_out;

    zero_counts<<<(G_ + 255) / 256, 256>>>();
    hist_kernel<<<(NB_ + 255) / 256, 256>>>(bo);
    scan_kernel<<<1, 1024>>>();
    scatter_kernel<<<(NB_ + 255) / 256, 256>>>(bi, bo);
    transpose_kernel<<<dim3(D_ / 32, BATCH_ / 32), dim3(32, 8)>>>(x);
    main_kernel<<<G_, 128>>>(x, w, out);
}

// round 6
// speedup vs baseline: 1.1675x; 1.1675x over previous
#include <cuda_runtime.h>
#include <cstdint>

// Fixed-shape problem: G=4000, B=8, DEG=32, BATCH=128
#define G_     4000
#define BSZ    8
#define NB_    132000               // G*DEG + G
#define BATCH_ 128
#define D_     32000                // G * BSZ
#define WCH    40                   // blocks staged per chunk

typedef unsigned long long ull;

// Scratch (no allocations allowed -> __device__ globals)
__device__ int   g_count[G_];
__device__ int   g_off[G_];
__device__ int   g_cur[G_];
__device__ int2  g_entries[NB_];                 // (block id n, src group)
__device__ float g_xT[(size_t)D_ * BATCH_];      // xT[col * 128 + b]

// ---------------- transpose x (BATCH, D) -> xT (D, BATCH), fused counter zeroing ----------------

__global__ void transpose_kernel(const float* __restrict__ x) {
    __shared__ float tile[32][33];
    int c0 = blockIdx.x * 32;  // along D   (grid.x = 1000)
    int r0 = blockIdx.y * 32;  // along BATCH (grid.y = 4)
    int tx = threadIdx.x, ty = threadIdx.y;  // (32, 8)

    // fused: zero g_count (blocks with y==0 cover 1000*256 >= 4000 slots)
    if (blockIdx.y == 0) {
        int i = blockIdx.x * 256 + ty * 32 + tx;
        if (i < G_) g_count[i] = 0;
    }

#pragma unroll
    for (int r = 0; r < 4; r++)
        tile[ty + 8 * r][tx] = x[(size_t)(r0 + ty + 8 * r) * D_ + (c0 + tx)];
    __syncthreads();
#pragma unroll
    for (int r = 0; r < 4; r++)
        g_xT[(size_t)(c0 + ty + 8 * r) * BATCH_ + (r0 + tx)] = tile[tx][ty + 8 * r];
}

// ---------------- counting sort by block_out ----------------

__global__ void hist_kernel(const int* __restrict__ bo) {
    int n = blockIdx.x * blockDim.x + threadIdx.x;
    if (n < NB_) atomicAdd(&g_count[bo[n]], 1);
}

__global__ void scan_kernel() {
    __shared__ int ssum[1024];
    int t = threadIdx.x;
    int base = t * 4;
    int v[4];
    int s = 0;
#pragma unroll
    for (int k = 0; k < 4; k++) {
        int c = (base + k < G_) ? g_count[base + k] : 0;
        v[k] = s;
        s += c;
    }
    ssum[t] = s;
    __syncthreads();
    for (int off = 1; off < 1024; off <<= 1) {
        int add = (t >= off) ? ssum[t - off] : 0;
        __syncthreads();
        ssum[t] += add;
        __syncthreads();
    }
    int tbase = ssum[t] - s;
#pragma unroll
    for (int k = 0; k < 4; k++) {
        if (base + k < G_) {
            int o = tbase + v[k];
            g_off[base + k] = o;
            g_cur[base + k] = o;
        }
    }
}

__global__ void scatter_kernel(const int* __restrict__ bi, const int* __restrict__ bo) {
    int n = blockIdx.x * blockDim.x + threadIdx.x;
    if (n < NB_) {
        int p = atomicAdd(&g_cur[bo[n]], 1);
        g_entries[p] = make_int2(n, bi[n]);
    }
}

// ---------------- main: per output group, batch-packed f32x2 GEMM ----------------

__device__ __forceinline__ void ffma2(ull& d, ull a, ull b) {
    asm("fma.rn.f32x2 %0, %1, %2, %0;" : "+l"(d) : "l"(a), "l"(b));
}

__global__ void __launch_bounds__(128) main_kernel(const float* __restrict__ x,
                                                   const float* __restrict__ w,
                                                   float* __restrict__ out) {
    // sw: WCH blocks of 64 duplicated w-pairs (20.5 KB); reused as the
    // cross-warp reduction buffer [4][128][9] floats (18 KB) afterwards.
    __shared__ __align__(16) ull sw[WCH * 64];
    __shared__ int ssrc[WCH];

    int g = blockIdx.x;
    int tid = threadIdx.x;
    int lane = tid & 31, wid = tid >> 5;
    int start = g_off[g];
    int cnt   = g_count[g];

    // acc[p][o]: packed pair of batch columns (4*lane+2p, 4*lane+2p+1), output o
    ull acc[2][8];
#pragma unroll
    for (int p = 0; p < 2; p++)
#pragma unroll
        for (int o = 0; o < 8; o++) acc[p][o] = 0;

    for (int c0 = 0; c0 < cnt; c0 += WCH) {
        int m = cnt - c0;
        if (m > WCH) m = WCH;

        if (tid < m) ssrc[tid] = g_entries[start + c0 + tid].y;

        // stage w blocks as duplicated f32 pairs (64 ULL per block)
        for (int idx = tid; idx < m * 64; idx += 128) {
            int j = idx >> 6, f = idx & 63;
            int n = g_entries[start + c0 + j].x;   // same addr across 64 threads -> broadcast
            unsigned u = __float_as_uint(w[(size_t)n * 64 + f]);
            sw[j * 64 + f] = ((ull)u << 32) | (ull)u;
        }
        __syncthreads();

        // each warp handles a disjoint subset of the staged blocks, all 128 columns
        for (int j = wid; j < m; j += 4) {
            int src = ssrc[j];
            const float4* xp = (const float4*)(g_xT + (size_t)src * (BSZ * BATCH_)) + lane;
            const ull* wp = sw + j * 64;
#pragma unroll
            for (int i = 0; i < 8; i++) {
                float4 xv = xp[i * 32];            // coalesced 512B per warp
                ull xa, xb;
                asm("mov.b64 %0, {%1, %2};" : "=l"(xa) : "f"(xv.x), "f"(xv.y));
                asm("mov.b64 %0, {%1, %2};" : "=l"(xb) : "f"(xv.z), "f"(xv.w));
#pragma unroll
                for (int q = 0; q < 4; q++) {
                    ulonglong2 wv = *(const ulonglong2*)(wp + i * 8 + q * 2);  // broadcast LDS.128
                    ffma2(acc[0][q * 2],     xa, wv.x);
                    ffma2(acc[0][q * 2 + 1], xa, wv.y);
                    ffma2(acc[1][q * 2],     xb, wv.x);
                    ffma2(acc[1][q * 2 + 1], xb, wv.y);
                }
            }
        }
        __syncthreads();
    }

    // cross-warp reduction through smem (padded stride 9 to avoid conflicts)
    float* sred = (float*)sw;   // [4][128][9]
#pragma unroll
    for (int p = 0; p < 2; p++)
#pragma unroll
        for (int o = 0; o < 8; o++) {
            int col = lane * 4 + p * 2;
            float lo = __uint_as_float((unsigned)(acc[p][o] & 0xffffffffu));
            float hi = __uint_as_float((unsigned)(acc[p][o] >> 32));
            sred[(wid * 128 + col) * 9 + o]     = lo;
            sred[(wid * 128 + col + 1) * 9 + o] = hi;
        }
    __syncthreads();

    // thread t = batch column: sum 4 warp partials, add residual, store
    int b = tid;
    size_t obase = (size_t)b * D_ + (size_t)g * 8;
    float4 r0 = *(const float4*)(x + obase);
    float4 r1 = *(const float4*)(x + obase + 4);
    float s[8];
#pragma unroll
    for (int o = 0; o < 8; o++) {
        float v = 0.f;
#pragma unroll
        for (int k = 0; k < 4; k++) v += sred[(k * 128 + b) * 9 + o];
        s[o] = v;
    }
    float4 o0 = make_float4(r0.x + s[0], r0.y + s[1], r0.z + s[2], r0.w + s[3]);
    float4 o1 = make_float4(r1.x + s[4], r1.y + s[5], r1.z + s[6], r1.w + s[7]);
    *(float4*)(out + obase)     = o0;
    *(float4*)(out + obase + 4) = o1;
}

// ---------------- launch ----------------

extern "C" void kernel_launch(void* const* d_in, const int* in_sizes, int n_in,
                              void* d_out, int out_size) {
    const float* x  = (const float*)d_in[0];   // (128, 32000) f32
    const float* w  = (const float*)d_in[1];   // (132000, 8, 8) f32
    const int*   bi = (const int*)d_in[2];     // block_in
    const int*   bo = (const int*)d_in[3];     // block_out
    float* out = (float*)d_out;

    transpose_kernel<<<dim3(D_ / 32, BATCH_ / 32), dim3(32, 8)>>>(x);   // + zero counts
    hist_kernel<<<(NB_ + 255) / 256, 256>>>(bo);
    scan_kernel<<<1, 1024>>>();
    scatter_kernel<<<(NB_ + 255) / 256, 256>>>(bi, bo);
    main_kernel<<<G_, 128>>>(x, w, out);
}

// round 7
// speedup vs baseline: 1.3551x; 1.1607x over previous
#include <cuda_runtime.h>
#include <cuda_fp16.h>
#include <cstdint>

// Fixed-shape problem: G=4000, B=8, DEG=32, BATCH=128
#define G_     4000
#define BSZ    8
#define NB_    132000               // G*DEG + G
#define BATCH_ 128
#define D_     32000                // G * BSZ
#define WCH    64                   // blocks staged per chunk (covers ~all groups in 1 chunk)
#define CAP    128                  // per-group bin capacity (max count ~60, 17-sigma safe)

typedef unsigned long long ull;

// Scratch (no allocations allowed -> __device__ globals)
__device__ int    g_cnt[G_];
__device__ int2   g_bin[(size_t)G_ * CAP];        // (block id n, src group)
__device__ __half g_xTh[(size_t)D_ * BATCH_];     // fp16 xT[col * 128 + b]

// ---------------- transpose x (BATCH, D) -> fp16 xT (D, BATCH), fused bin-count zeroing ----------------

__global__ void transpose_kernel(const float* __restrict__ x) {
    __shared__ float tile[32][33];
    int c0 = blockIdx.x * 32;  // along D     (grid.x = 1000)
    int r0 = blockIdx.y * 32;  // along BATCH (grid.y = 4)
    int tx = threadIdx.x, ty = threadIdx.y;  // (32, 8)

    // fused: zero g_cnt (blocks with y==0 cover 1000*256 >= 4000 slots)
    if (blockIdx.y == 0) {
        int i = blockIdx.x * 256 + ty * 32 + tx;
        if (i < G_) g_cnt[i] = 0;
    }

#pragma unroll
    for (int r = 0; r < 4; r++)
        tile[ty + 8 * r][tx] = x[(size_t)(r0 + ty + 8 * r) * D_ + (c0 + tx)];
    __syncthreads();
#pragma unroll
    for (int r = 0; r < 4; r++)
        g_xTh[(size_t)(c0 + ty + 8 * r) * BATCH_ + (r0 + tx)] =
            __float2half_rn(tile[tx][ty + 8 * r]);
}

// ---------------- direct bin scatter (replaces hist + scan + scatter) ----------------

__global__ void scatter_kernel(const int* __restrict__ bi, const int* __restrict__ bo) {
    int i0 = (blockIdx.x * blockDim.x + threadIdx.x) * 4;   // NB_ % 4 == 0
    if (i0 >= NB_) return;
    int4 vin = *(const int4*)(bi + i0);
    int4 vout = *(const int4*)(bo + i0);
#pragma unroll
    for (int k = 0; k < 4; k++) {
        int src = (&vin.x)[k];
        int dst = (&vout.x)[k];
        int p = atomicAdd(&g_cnt[dst], 1);
        g_bin[(size_t)dst * CAP + p] = make_int2(i0 + k, src);
    }
}

// ---------------- main: per output group, batch-packed f32x2 GEMM over fp16 x ----------------

__device__ __forceinline__ void ffma2(ull& d, ull a, ull b) {
    asm("fma.rn.f32x2 %0, %1, %2, %0;" : "+l"(d) : "l"(a), "l"(b));
}

__global__ void __launch_bounds__(128) main_kernel(const float* __restrict__ x,
                                                   const float* __restrict__ w,
                                                   float* __restrict__ out) {
    // sw: WCH blocks of 64 duplicated fp32 w-pairs (32 KB);
    // reused afterwards as the cross-warp reduction buffer [4][128][9] f32 (18 KB).
    __shared__ __align__(16) ull sw[WCH * 64];
    __shared__ int ssrc[WCH];

    int g = blockIdx.x;
    int tid = threadIdx.x;
    int lane = tid & 31, wid = tid >> 5;
    int cnt = g_cnt[g];
    const int2* bin = g_bin + (size_t)g * CAP;

    // acc[p][o]: packed pair of batch columns (4*lane + 2p, 4*lane + 2p + 1), output o
    ull acc[2][8];
#pragma unroll
    for (int p = 0; p < 2; p++)
#pragma unroll
        for (int o = 0; o < 8; o++) acc[p][o] = 0;

    for (int c0 = 0; c0 < cnt; c0 += WCH) {
        int m = cnt - c0;
        if (m > WCH) m = WCH;

        if (tid < m) ssrc[tid] = bin[c0 + tid].y;

        // stage m w-blocks as duplicated f32 pairs (64 ULL per block)
        for (int idx = tid; idx < m * 64; idx += 128) {
            int j = idx >> 6, f = idx & 63;
            int n = bin[c0 + j].x;                 // same addr across 64 threads -> broadcast
            unsigned u = __float_as_uint(w[(size_t)n * 64 + f]);
            sw[j * 64 + f] = ((ull)u << 32) | (ull)u;
        }
        __syncthreads();

        // each warp handles a disjoint subset of staged blocks, all 128 columns
        for (int j = wid; j < m; j += 4) {
            int src = ssrc[j];
            const uint2* xp = (const uint2*)(g_xTh + (size_t)src * (BSZ * BATCH_)) + lane;
            const ull* wp = sw + j * 64;

            // batch all 8 row-loads first (MLP=8, 256B/warp each, coalesced)
            uint2 xv[8];
#pragma unroll
            for (int i = 0; i < 8; i++) xv[i] = xp[i * 32];

#pragma unroll
            for (int i = 0; i < 8; i++) {
                float2 f01 = __half22float2(*(const __half2*)&xv[i].x);
                float2 f23 = __half22float2(*(const __half2*)&xv[i].y);
                ull xa, xb;
                asm("mov.b64 %0, {%1, %2};" : "=l"(xa) : "f"(f01.x), "f"(f01.y));
                asm("mov.b64 %0, {%1, %2};" : "=l"(xb) : "f"(f23.x), "f"(f23.y));
#pragma unroll
                for (int q = 0; q < 4; q++) {
                    ulonglong2 wv = *(const ulonglong2*)(wp + i * 8 + q * 2);  // broadcast LDS.128
                    ffma2(acc[0][q * 2],     xa, wv.x);
                    ffma2(acc[0][q * 2 + 1], xa, wv.y);
                    ffma2(acc[1][q * 2],     xb, wv.x);
                    ffma2(acc[1][q * 2 + 1], xb, wv.y);
                }
            }
        }
        __syncthreads();
    }

    // cross-warp reduction through smem (padded stride 9, conflict-free)
    float* sred = (float*)sw;   // [4][128][9]
#pragma unroll
    for (int p = 0; p < 2; p++)
#pragma unroll
        for (int o = 0; o < 8; o++) {
            int col = lane * 4 + p * 2;
            float lo = __uint_as_float((unsigned)(acc[p][o] & 0xffffffffu));
            float hi = __uint_as_float((unsigned)(acc[p][o] >> 32));
            sred[(wid * 128 + col) * 9 + o]     = lo;
            sred[(wid * 128 + col + 1) * 9 + o] = hi;
        }
    __syncthreads();

    // thread t = batch column: sum 4 warp partials, add fp32 residual, store
    int b = tid;
    size_t obase = (size_t)b * D_ + (size_t)g * 8;
    float4 r0 = *(const float4*)(x + obase);
    float4 r1 = *(const float4*)(x + obase + 4);
    float s[8];
#pragma unroll
    for (int o = 0; o < 8; o++) {
        float v = 0.f;
#pragma unroll
        for (int k = 0; k < 4; k++) v += sred[(k * 128 + b) * 9 + o];
        s[o] = v;
    }
    float4 o0 = make_float4(r0.x + s[0], r0.y + s[1], r0.z + s[2], r0.w + s[3]);
    float4 o1 = make_float4(r1.x + s[4], r1.y + s[5], r1.z + s[6], r1.w + s[7]);
    *(float4*)(out + obase)     = o0;
    *(float4*)(out + obase + 4) = o1;
}

// ---------------- launch ----------------

extern "C" void kernel_launch(void* const* d_in, const int* in_sizes, int n_in,
                              void* d_out, int out_size) {
    const float* x  = (const float*)d_in[0];   // (128, 32000) f32
    const float* w  = (const float*)d_in[1];   // (132000, 8, 8) f32
    const int*   bi = (const int*)d_in[2];     // block_in
    const int*   bo = (const int*)d_in[3];     // block_out
    float* out = (float*)d_out;

    transpose_kernel<<<dim3(D_ / 32, BATCH_ / 32), dim3(32, 8)>>>(x);  // + zero bin counts
    scatter_kernel<<<(NB_ / 4 + 255) / 256, 256>>>(bi, bo);
    main_kernel<<<G_, 128>>>(x, w, out);
}

// round 8
// speedup vs baseline: 1.3883x; 1.0245x over previous
#include <cuda_runtime.h>
#include <cuda_fp16.h>
#include <cstdint>

// Fixed-shape problem: G=4000, B=8, DEG=32, BATCH=128
#define G_     4000
#define BSZ    8
#define NB_    132000               // G*DEG + G
#define BATCH_ 128
#define D_     32000                // G * BSZ
#define WCH    64                   // blocks staged per chunk (max group count ~56)
#define CAP    128                  // per-group bin capacity
#define SCAT_CTAS ((NB_ + 1023) / 1024)   // 129 scatter CTAs (256 thr x 4 elem)

typedef unsigned long long ull;

// Scratch (no allocations allowed -> __device__ globals; zero-initialized once)
__device__ int    g_cnt[G_];                      // re-zeroed by main_kernel each run
__device__ int2   g_bin[(size_t)G_ * CAP];        // (block id n, src group)
__device__ __half g_xTh[(size_t)D_ * BATCH_];     // fp16 xT[col * 128 + b]

// ---------------- fused pre-kernel: transpose (CTAs 0..3999) + bin scatter (rest) ----

__global__ void __launch_bounds__(256) pre_kernel(const float* __restrict__ x,
                                                  const int* __restrict__ bi,
                                                  const int* __restrict__ bo) {
    int bid = blockIdx.x;
    if (bid < 4000) {
        // ---- transpose x (BATCH, D) -> fp16 xT (D, BATCH) ----
        __shared__ float tile[32][33];
        int c0 = (bid & 1023) >= 1000 ? 0 : 0;  // (placeholder no-op)
        int bx = bid % 1000, by = bid / 1000;
        c0 = bx * 32;                 // along D
        int r0 = by * 32;             // along BATCH
        int tx = threadIdx.x & 31, ty = threadIdx.x >> 5;  // (32, 8)
#pragma unroll
        for (int r = 0; r < 4; r++)
            tile[ty + 8 * r][tx] = x[(size_t)(r0 + ty + 8 * r) * D_ + (c0 + tx)];
        __syncthreads();
        // vectorized store: thread t -> row d = t>>3 of D, 4 batch cols bq..bq+3
        int t = threadIdx.x;
        int d = t >> 3;
        int bq = (t & 7) * 4;
        __half h[4];
#pragma unroll
        for (int k = 0; k < 4; k++) h[k] = __float2half_rn(tile[bq + k][d]);
        *(uint2*)&g_xTh[(size_t)(c0 + d) * BATCH_ + r0 + bq] = *(const uint2*)h;
    } else {
        // ---- direct bin scatter (g_cnt pre-zeroed by previous main_kernel) ----
        int i0 = ((bid - 4000) * 256 + threadIdx.x) * 4;
        if (i0 >= NB_) return;
        int4 vin  = *(const int4*)(bi + i0);
        int4 vout = *(const int4*)(bo + i0);
#pragma unroll
        for (int k = 0; k < 4; k++) {
            int src = (&vin.x)[k];
            int dst = (&vout.x)[k];
            int p = atomicAdd(&g_cnt[dst], 1);
            g_bin[(size_t)dst * CAP + p] = make_int2(i0 + k, src);
        }
    }
}

// ---------------- main: per output group, batch-packed f32x2 GEMM over fp16 x ------

__device__ __forceinline__ void ffma2(ull& d, ull a, ull b) {
    asm("fma.rn.f32x2 %0, %1, %2, %0;" : "+l"(d) : "l"(a), "l"(b));
}

__global__ void __launch_bounds__(128) main_kernel(const float* __restrict__ x,
                                                   const float* __restrict__ w,
                                                   float* __restrict__ out) {
    // sw: WCH blocks of 64 duplicated fp32 w-pairs (32 KB);
    // reused afterwards as the cross-warp reduction buffer [4][128][9] f32 (18 KB).
    __shared__ __align__(16) ull sw[WCH * 64];
    __shared__ int ssrc[WCH];

    int g = blockIdx.x;
    int tid = threadIdx.x;
    int lane = tid & 31, wid = tid >> 5;
    int cnt = g_cnt[g];
    const int2* bin = g_bin + (size_t)g * CAP;

    // acc[p][o]: packed pair of batch columns (4*lane + 2p, 4*lane + 2p + 1), output o
    ull acc[2][8];
#pragma unroll
    for (int p = 0; p < 2; p++)
#pragma unroll
        for (int o = 0; o < 8; o++) acc[p][o] = 0;

    for (int c0 = 0; c0 < cnt; c0 += WCH) {
        int m = cnt - c0;
        if (m > WCH) m = WCH;

        if (tid < m) ssrc[tid] = bin[c0 + tid].y;

        // stage m w-blocks as duplicated f32 pairs (64 ULL per block)
        for (int idx = tid; idx < m * 64; idx += 128) {
            int j = idx >> 6, f = idx & 63;
            int n = bin[c0 + j].x;                 // broadcast across 64 threads
            unsigned u = __float_as_uint(w[(size_t)n * 64 + f]);
            sw[j * 64 + f] = ((ull)u << 32) | (ull)u;
        }
        __syncthreads();

        // each warp: disjoint subset of staged blocks, software-pipelined x gather
        int j = wid;
        uint2 xv[8];
        if (j < m) {
            const uint2* xp = (const uint2*)(g_xTh + (size_t)ssrc[j] * (BSZ * BATCH_)) + lane;
#pragma unroll
            for (int i = 0; i < 8; i++) xv[i] = xp[i * 32];
        }
        for (; j < m; j += 4) {
            // prefetch next block's x while this block computes (hides L2 latency)
            uint2 xn[8];
            int jn = j + 4;
            if (jn < m) {
                const uint2* xp = (const uint2*)(g_xTh + (size_t)ssrc[jn] * (BSZ * BATCH_)) + lane;
#pragma unroll
                for (int i = 0; i < 8; i++) xn[i] = xp[i * 32];
            }

            const ull* wp = sw + j * 64;
#pragma unroll
            for (int i = 0; i < 8; i++) {
                float2 f01 = __half22float2(*(const __half2*)&xv[i].x);
                float2 f23 = __half22float2(*(const __half2*)&xv[i].y);
                ull xa, xb;
                asm("mov.b64 %0, {%1, %2};" : "=l"(xa) : "f"(f01.x), "f"(f01.y));
                asm("mov.b64 %0, {%1, %2};" : "=l"(xb) : "f"(f23.x), "f"(f23.y));
#pragma unroll
                for (int q = 0; q < 4; q++) {
                    ulonglong2 wv = *(const ulonglong2*)(wp + i * 8 + q * 2);  // broadcast LDS.128
                    ffma2(acc[0][q * 2],     xa, wv.x);
                    ffma2(acc[0][q * 2 + 1], xa, wv.y);
                    ffma2(acc[1][q * 2],     xb, wv.x);
                    ffma2(acc[1][q * 2 + 1], xb, wv.y);
                }
            }

            if (jn < m) {
#pragma unroll
                for (int i = 0; i < 8; i++) xv[i] = xn[i];
            }
        }
        __syncthreads();
    }

    // re-zero this group's counter for the next graph replay
    if (tid == 0) g_cnt[g] = 0;

    // cross-warp reduction through smem (padded stride 9, conflict-free)
    float* sred = (float*)sw;   // [4][128][9]
#pragma unroll
    for (int p = 0; p < 2; p++)
#pragma unroll
        for (int o = 0; o < 8; o++) {
            int col = lane * 4 + p * 2;
            float lo = __uint_as_float((unsigned)(acc[p][o] & 0xffffffffu));
            float hi = __uint_as_float((unsigned)(acc[p][o] >> 32));
            sred[(wid * 128 + col) * 9 + o]     = lo;
            sred[(wid * 128 + col + 1) * 9 + o] = hi;
        }
    __syncthreads();

    // thread t = batch column: sum 4 warp partials, add fp32 residual, store
    int b = tid;
    size_t obase = (size_t)b * D_ + (size_t)g * 8;
    float4 r0 = *(const float4*)(x + obase);
    float4 r1 = *(const float4*)(x + obase + 4);
    float s[8];
#pragma unroll
    for (int o = 0; o < 8; o++) {
        float v = 0.f;
#pragma unroll
        for (int k = 0; k < 4; k++) v += sred[(k * 128 + b) * 9 + o];
        s[o] = v;
    }
    float4 o0 = make_float4(r0.x + s[0], r0.y + s[1], r0.z + s[2], r0.w + s[3]);
    float4 o1 = make_float4(r1.x + s[4], r1.y + s[5], r1.z + s[6], r1.w + s[7]);
    *(float4*)(out + obase)     = o0;
    *(float4*)(out + obase + 4) = o1;
}

// ---------------- launch ----------------

extern "C" void kernel_launch(void* const* d_in, const int* in_sizes, int n_in,
                              void* d_out, int out_size) {
    const float* x  = (const float*)d_in[0];   // (128, 32000) f32
    const float* w  = (const float*)d_in[1];   // (132000, 8, 8) f32
    const int*   bi = (const int*)d_in[2];     // block_in
    const int*   bo = (const int*)d_in[3];     // block_out
    float* out = (float*)d_out;

    pre_kernel<<<4000 + SCAT_CTAS, 256>>>(x, bi, bo);   // transpose + scatter fused
    main_kernel<<<G_, 128>>>(x, w, out);
}

// round 9
// speedup vs baseline: 1.6055x; 1.1564x over previous
#include <cuda_runtime.h>
#include <cuda_fp16.h>
#include <cstdint>

// Fixed-shape problem: G=4000, B=8, DEG=32, BATCH=128
#define G_     4000
#define NB_    132000               // G*DEG + G
#define BATCH_ 128
#define D_     32000                // G * BSZ
#define CAP    128                  // per-group bin capacity (max cnt ~60)
#define CCH    6                    // block-PAIRS staged per chunk
#define SXS    136                  // sx row stride in halves (272B: conflict-free ldmatrix)
#define WSS    24                   // ws row stride in halves (48B: conflict-free ldmatrix)
#define SCAT_CTAS ((NB_ + 1023) / 1024)

// Scratch (no allocations allowed -> __device__ globals; zero-init on load)
__device__ int    g_cnt[G_];                      // re-zeroed by main_kernel each run
__device__ int2   g_bin[(size_t)G_ * CAP];        // (block id n, src group)
__device__ __half g_xTh[(size_t)D_ * BATCH_];     // fp16 xT[col * 128 + b]

// ---------------- fused pre-kernel: transpose (CTAs 0..3999) + bin scatter ----------

__global__ void __launch_bounds__(256) pre_kernel(const float* __restrict__ x,
                                                  const int* __restrict__ bi,
                                                  const int* __restrict__ bo) {
    int bid = blockIdx.x;
    if (bid < 4000) {
        __shared__ float tile[32][33];
        int bx = bid % 1000, by = bid / 1000;
        int c0 = bx * 32;             // along D
        int r0 = by * 32;             // along BATCH
        int tx = threadIdx.x & 31, ty = threadIdx.x >> 5;
#pragma unroll
        for (int r = 0; r < 4; r++)
            tile[ty + 8 * r][tx] = x[(size_t)(r0 + ty + 8 * r) * D_ + (c0 + tx)];
        __syncthreads();
        int t = threadIdx.x;
        int d = t >> 3;
        int bq = (t & 7) * 4;
        __half h[4];
#pragma unroll
        for (int k = 0; k < 4; k++) h[k] = __float2half_rn(tile[bq + k][d]);
        *(uint2*)&g_xTh[(size_t)(c0 + d) * BATCH_ + r0 + bq] = *(const uint2*)h;
    } else {
        int i0 = ((bid - 4000) * 256 + threadIdx.x) * 4;
        if (i0 >= NB_) return;
        int4 vin  = *(const int4*)(bi + i0);
        int4 vout = *(const int4*)(bo + i0);
#pragma unroll
        for (int k = 0; k < 4; k++) {
            int src = (&vin.x)[k];
            int dst = (&vout.x)[k];
            int p = atomicAdd(&g_cnt[dst], 1);
            g_bin[(size_t)dst * CAP + p] = make_int2(i0 + k, src);
        }
    }
}

// ---------------- tensor-core main ----------------

__device__ __forceinline__ void ldsm4t(uint32_t& r0, uint32_t& r1, uint32_t& r2,
                                       uint32_t& r3, uint32_t addr) {
    asm volatile("ldmatrix.sync.aligned.m8n8.x4.trans.shared.b16 {%0,%1,%2,%3}, [%4];"
                 : "=r"(r0), "=r"(r1), "=r"(r2), "=r"(r3) : "r"(addr));
}

__device__ __forceinline__ void mma16816(float* c, uint32_t a0, uint32_t a1, uint32_t a2,
                                         uint32_t a3, uint32_t b0, uint32_t b1) {
    asm volatile("mma.sync.aligned.m16n8k16.row.col.f32.f16.f16.f32 "
                 "{%0,%1,%2,%3}, {%4,%5,%6,%7}, {%8,%9}, {%0,%1,%2,%3};"
                 : "+f"(c[0]), "+f"(c[1]), "+f"(c[2]), "+f"(c[3])
                 : "r"(a0), "r"(a1), "r"(a2), "r"(a3), "r"(b0), "r"(b1));
}

__global__ void __launch_bounds__(128) main_kernel(const float* __restrict__ x,
                                                   const float* __restrict__ w,
                                                   float* __restrict__ out) {
    // sx: CCH pairs of stacked x tiles [16 k-rows][128 b], padded stride.
    // ws: CCH w tiles [16 k-rows][16 o] (o 8-15 zero), padded stride.
    __shared__ __align__(16) __half sx[CCH * 16 * SXS];   // 26112 B (aliased as sred)
    __shared__ __align__(16) __half ws[CCH * 16 * WSS];   //  4608 B

    int g = blockIdx.x;
    int tid = threadIdx.x, lane = tid & 31, wid = tid >> 5;
    int cnt = g_cnt[g];
    const int2* bin = g_bin + (size_t)g * CAP;
    int npairs = (cnt + 1) >> 1;

    uint32_t sx_u, ws_u;
    asm("{ .reg .u64 t; cvta.to.shared.u64 t, %1; cvt.u32.u64 %0, t; }" : "=r"(sx_u) : "l"(sx));
    asm("{ .reg .u64 t; cvta.to.shared.u64 t, %1; cvt.u32.u64 %0, t; }" : "=r"(ws_u) : "l"(ws));

    // D frags: acc[q][0..3]; q = n-slice (8 b each). Only c0,c1 (o rows 0-7) used at end.
    float acc[4][4];
#pragma unroll
    for (int q = 0; q < 4; q++)
#pragma unroll
        for (int r = 0; r < 4; r++) acc[q][r] = 0.f;

    for (int pc = 0; pc < npairs; pc += CCH) {
        int mp = npairs - pc;
        if (mp > CCH) mp = CCH;
        __syncthreads();   // previous chunk's ldmatrix reads complete

        // ---- stage x: mp*16 rows of 256B, 16 threads x LDG.128/STS.128 per row ----
        for (int row = tid >> 4; row < mp * 16; row += 8) {
            int p = row >> 4, k = row & 15;
            int jb = (pc + p) * 2 + (k >> 3);
            int src = (jb < cnt) ? bin[jb].y : bin[(pc + p) * 2].y;   // dummy: any valid x
            const uint4* s = (const uint4*)(g_xTh + ((size_t)src * 8 + (k & 7)) * BATCH_)
                             + (tid & 15);
            *(uint4*)(sx + (size_t)(p * 16 + k) * SXS + (tid & 15) * 8) = *s;
        }
        // ---- stage w (f32 -> fp16), zero-pad o 8-15 ----
        {
            int k = tid >> 3, o = tid & 7;   // 128 threads = 16 x 8
            for (int p = 0; p < mp; p++) {
                int jb = (pc + p) * 2 + (k >> 3);
                __half hv = __float2half_rn(0.f);
                if (jb < cnt) {
                    int n = bin[jb].x;
                    hv = __float2half_rn(w[(size_t)n * 64 + (k & 7) * 8 + o]);
                }
                __half* wr = ws + (p * 16 + k) * WSS;
                wr[o]     = hv;
                wr[o + 8] = __float2half_rn(0.f);
            }
        }
        __syncthreads();

        // ---- mma over staged pairs; each warp owns b columns [32*wid, 32*wid+32) ----
        int r8 = lane & 7, t4 = lane >> 3;
        for (int p = 0; p < mp; p++) {
            // A = [w_j^T | w_j2^T] via ldmatrix.trans of ws[k][o]
            uint32_t a0, a1, a2, a3;
            {
                uint32_t addr = ws_u + ((p * 16 + r8 + ((t4 >> 1) << 3)) * WSS
                                        + ((t4 & 1) << 3)) * 2;
                ldsm4t(a0, a1, a2, a3, addr);
            }
            // B frags from sx[k][b]: tiles (k-lo/hi) x (n-slice)
            uint32_t b00, b01, b10, b11, b20, b21, b30, b31;
            {
                uint32_t addr = sx_u + ((size_t)0, ((p * 16 + r8 + ((t4 & 1) << 3)) * SXS
                                        + wid * 32 + ((t4 >> 1) << 3)) * 2);
                ldsm4t(b00, b01, b10, b11, addr);          // q0 (b0,b1), q1 (b0,b1)
                ldsm4t(b20, b21, b30, b31, addr + 32);     // +16 cols: q2, q3
            }
            mma16816(acc[0], a0, a1, a2, a3, b00, b01);
            mma16816(acc[1], a0, a1, a2, a3, b10, b11);
            mma16816(acc[2], a0, a1, a2, a3, b20, b21);
            mma16816(acc[3], a0, a1, a2, a3, b30, b31);
        }
    }

    // ---- epilogue: frags -> smem [8 o][132 b], then residual + coalesced-per-thread store ----
    __syncthreads();
    float* sred = (float*)sx;   // 8*132*4 = 4224 B, fits in sx
#pragma unroll
    for (int q = 0; q < 4; q++) {
        int o = lane >> 2;
        int b = wid * 32 + q * 8 + ((lane & 3) << 1);
        sred[o * 132 + b]     = acc[q][0];
        sred[o * 132 + b + 1] = acc[q][1];
    }
    __syncthreads();

    if (tid == 0) g_cnt[g] = 0;   // ready for next graph replay

    int b = tid;
    size_t obase = (size_t)b * D_ + (size_t)g * 8;
    float4 r0 = *(const float4*)(x + obase);
    float4 r1 = *(const float4*)(x + obase + 4);
    float s[8];
#pragma unroll
    for (int o = 0; o < 8; o++) s[o] = sred[o * 132 + b];
    float4 o0 = make_float4(r0.x + s[0], r0.y + s[1], r0.z + s[2], r0.w + s[3]);
    float4 o1 = make_float4(r1.x + s[4], r1.y + s[5], r1.z + s[6], r1.w + s[7]);
    *(float4*)(out + obase)     = o0;
    *(float4*)(out + obase + 4) = o1;
}

// ---------------- launch ----------------

extern "C" void kernel_launch(void* const* d_in, const int* in_sizes, int n_in,
                              void* d_out, int out_size) {
    const float* x  = (const float*)d_in[0];   // (128, 32000) f32
    const float* w  = (const float*)d_in[1];   // (132000, 8, 8) f32
    const int*   bi = (const int*)d_in[2];     // block_in
    const int*   bo = (const int*)d_in[3];     // block_out
    float* out = (float*)d_out;

    pre_kernel<<<4000 + SCAT_CTAS, 256>>>(x, bi, bo);
    main_kernel<<<G_, 128>>>(x, w, out);
}

// round 11
// speedup vs baseline: 1.8652x; 1.1618x over previous
#include <cuda_runtime.h>
#include <cuda_fp16.h>
#include <cstdint>

// Fixed-shape problem: G=4000, B=8, DEG=32, BATCH=128
#define G_     4000
#define NB_    132000               // G*DEG + G
#define BATCH_ 128
#define D_     32000
#define CAP    128                  // per-group bin capacity (max cnt ~60)
#define STAGES 6                    // cp.async pipeline depth (block-pairs)
#define SXS    136                  // sx row stride in halves (272B: conflict-free ldmatrix)
#define STG_HALVES (16 * SXS)       // 2176 halves per stage
#define STG_BYTES  (STG_HALVES * 2) // 4352 B per stage
#define SCAT_CTAS ((NB_ + 1023) / 1024)

// Scratch (no allocations allowed -> __device__ globals; zero-init on load)
__device__ int    g_cnt[G_];                      // re-zeroed by main_kernel each run
__device__ int2   g_bin[(size_t)G_ * CAP];        // (block id n, src group)
__device__ __half g_xTh[(size_t)D_ * BATCH_];     // fp16 xT[col * 128 + b]

// ---------------- fused pre-kernel: transpose (CTAs 0..3999) + bin scatter ----------

__global__ void __launch_bounds__(256) pre_kernel(const float* __restrict__ x,
                                                  const int* __restrict__ bi,
                                                  const int* __restrict__ bo) {
    int bid = blockIdx.x;
    if (bid < 4000) {
        __shared__ float tile[32][33];
        int bx = bid % 1000, by = bid / 1000;
        int c0 = bx * 32;             // along D
        int r0 = by * 32;             // along BATCH
        int tx = threadIdx.x & 31, ty = threadIdx.x >> 5;
#pragma unroll
        for (int r = 0; r < 4; r++)
            tile[ty + 8 * r][tx] = x[(size_t)(r0 + ty + 8 * r) * D_ + (c0 + tx)];
        __syncthreads();
        int t = threadIdx.x;
        int d = t >> 3;
        int bq = (t & 7) * 4;
        __half h[4];
#pragma unroll
        for (int k = 0; k < 4; k++) h[k] = __float2half_rn(tile[bq + k][d]);
        *(uint2*)&g_xTh[(size_t)(c0 + d) * BATCH_ + r0 + bq] = *(const uint2*)h;
    } else {
        int i0 = ((bid - 4000) * 256 + threadIdx.x) * 4;
        if (i0 >= NB_) return;
        int4 vin  = *(const int4*)(bi + i0);
        int4 vout = *(const int4*)(bo + i0);
#pragma unroll
        for (int k = 0; k < 4; k++) {
            int src = (&vin.x)[k];
            int dst = (&vout.x)[k];
            int p = atomicAdd(&g_cnt[dst], 1);
            g_bin[(size_t)dst * CAP + p] = make_int2(i0 + k, src);
        }
    }
}

// ---------------- tensor-core main with cp.async pipeline ----------------

__device__ __forceinline__ void ldsm4t(uint32_t& r0, uint32_t& r1, uint32_t& r2,
                                       uint32_t& r3, uint32_t addr) {
    asm volatile("ldmatrix.sync.aligned.m8n8.x4.trans.shared.b16 {%0,%1,%2,%3}, [%4];"
                 : "=r"(r0), "=r"(r1), "=r"(r2), "=r"(r3) : "r"(addr));
}

__device__ __forceinline__ void mma16816(float* c, uint32_t a0, uint32_t a1, uint32_t a2,
                                         uint32_t a3, uint32_t b0, uint32_t b1) {
    asm volatile("mma.sync.aligned.m16n8k16.row.col.f32.f16.f16.f32 "
                 "{%0,%1,%2,%3}, {%4,%5,%6,%7}, {%8,%9}, {%0,%1,%2,%3};"
                 : "+f"(c[0]), "+f"(c[1]), "+f"(c[2]), "+f"(c[3])
                 : "r"(a0), "r"(a1), "r"(a2), "r"(a3), "r"(b0), "r"(b1));
}

__device__ __forceinline__ void cp16(uint32_t saddr, const void* gaddr) {
    asm volatile("cp.async.cg.shared.global [%0], [%1], 16;"
                 :: "r"(saddr), "l"(gaddr) : "memory");
}
__device__ __forceinline__ void cp_commit() {
    asm volatile("cp.async.commit_group;" ::: "memory");
}
template <int N>
__device__ __forceinline__ void cp_wait() {
    asm volatile("cp.async.wait_group %0;" :: "n"(N) : "memory");
}

__device__ __forceinline__ uint32_t packh2(float lo, float hi) {
    __half2 h = __halves2half2(__float2half_rn(lo), __float2half_rn(hi));
    return *(uint32_t*)&h;
}

__global__ void __launch_bounds__(128) main_kernel(const float* __restrict__ x,
                                                   const float* __restrict__ w,
                                                   float* __restrict__ out) {
    __shared__ __align__(16) __half sx[STAGES * STG_HALVES];   // 26112 B (aliased as sred)
    __shared__ int ssrc[CAP];   // src group per block
    __shared__ int snum[CAP];   // block id n per block

    int g = blockIdx.x;
    int tid = threadIdx.x, lane = tid & 31, wid = tid >> 5;
    int cnt = g_cnt[g];
    const int2* bin = g_bin + (size_t)g * CAP;

    if (tid < cnt) {
        int2 e = bin[tid];
        snum[tid] = e.x;
        ssrc[tid] = e.y;
    }
    __syncthreads();

    int npairs = (cnt + 1) >> 1;

    uint32_t sx_u;
    asm("{ .reg .u64 t; cvta.to.shared.u64 t, %1; cvt.u32.u64 %0, t; }" : "=r"(sx_u) : "l"(sx));

    // per-thread constants
    int kk  = tid >> 4;            // copy row 0..7
    int col = (tid & 15) * 8;      // copy column (halves)
    int gr  = lane >> 2;           // A frag: o row
    int c2  = (lane & 3) << 1;     // A frag: i col pair base
    int r8  = lane & 7, t4 = lane >> 3;
    uint32_t baddr_off = ((uint32_t)(r8 + ((t4 & 1) << 3)) * SXS
                          + (uint32_t)(wid * 32 + ((t4 >> 1) << 3))) * 2;

    float acc[4][4];
#pragma unroll
    for (int q = 0; q < 4; q++)
#pragma unroll
        for (int r = 0; r < 4; r++) acc[q][r] = 0.f;

    // ---- prologue: fill pipeline (always commit STAGES groups) ----
#pragma unroll
    for (int s = 0; s < STAGES; s++) {
        if (s < npairs) {
            int j0 = 2 * s, j1 = j0 + 1;
            int s0 = ssrc[j0];
            int s1 = (j1 < cnt) ? ssrc[j1] : s0;
            uint32_t d = sx_u + s * STG_BYTES + (uint32_t)(kk * SXS + col) * 2;
            cp16(d,                 g_xTh + ((size_t)s0 * 8 + kk) * BATCH_ + col);
            cp16(d + 8 * SXS * 2,   g_xTh + ((size_t)s1 * 8 + kk) * BATCH_ + col);
        }
        cp_commit();
    }

    // ---- A regs for pair 0 ----
    uint32_t ca0 = 0, ca2 = 0;
    {
        const float* wp = w + (size_t)snum[0] * 64 + c2 * 8 + gr;
        ca0 = packh2(wp[0], wp[8]);
        if (1 < cnt) {
            const float* wq = w + (size_t)snum[1] * 64 + c2 * 8 + gr;
            ca2 = packh2(wq[0], wq[8]);
        }
    }

    const uint32_t zero = 0;
    int st = 0;
    for (int p = 0; p < npairs; p++) {
        // prefetch A for pair p+1 (hides w latency under mma)
        uint32_t na0 = 0, na2 = 0;
        int pn = p + 1;
        if (pn < npairs) {
            const float* wp = w + (size_t)snum[2 * pn] * 64 + c2 * 8 + gr;
            na0 = packh2(wp[0], wp[8]);
            if (2 * pn + 1 < cnt) {
                const float* wq = w + (size_t)snum[2 * pn + 1] * 64 + c2 * 8 + gr;
                na2 = packh2(wq[0], wq[8]);
            }
        }

        cp_wait<STAGES - 1>();   // group p complete
        __syncthreads();

        uint32_t addr = sx_u + st * STG_BYTES + baddr_off;
        uint32_t b00, b01, b10, b11, b20, b21, b30, b31;
        ldsm4t(b00, b01, b10, b11, addr);
        ldsm4t(b20, b21, b30, b31, addr + 32);
        mma16816(acc[0], ca0, zero, ca2, zero, b00, b01);
        mma16816(acc[1], ca0, zero, ca2, zero, b10, b11);
        mma16816(acc[2], ca0, zero, ca2, zero, b20, b21);
        mma16816(acc[3], ca0, zero, ca2, zero, b30, b31);

        __syncthreads();         // stage st free for rewrite

        int pf = p + STAGES;     // refill stage st with pair pf (pf % STAGES == st)
        if (pf < npairs) {
            int j0 = 2 * pf, j1 = j0 + 1;
            int s0 = ssrc[j0];
            int s1 = (j1 < cnt) ? ssrc[j1] : s0;
            uint32_t d = sx_u + st * STG_BYTES + (uint32_t)(kk * SXS + col) * 2;
            cp16(d,               g_xTh + ((size_t)s0 * 8 + kk) * BATCH_ + col);
            cp16(d + 8 * SXS * 2, g_xTh + ((size_t)s1 * 8 + kk) * BATCH_ + col);
        }
        cp_commit();

        ca0 = na0; ca2 = na2;
        st = (st + 1 == STAGES) ? 0 : st + 1;
    }

    // ---- epilogue: frags -> smem [8 o][132 b], residual, coalesced-per-thread store ----
    __syncthreads();
    float* sred = (float*)sx;   // 8*132*4 = 4224 B
#pragma unroll
    for (int q = 0; q < 4; q++) {
        int o = lane >> 2;
        int b = wid * 32 + q * 8 + ((lane & 3) << 1);
        sred[o * 132 + b]     = acc[q][0];
        sred[o * 132 + b + 1] = acc[q][1];
    }
    __syncthreads();

    if (tid == 0) g_cnt[g] = 0;   // ready for next graph replay

    int b = tid;
    size_t obase = (size_t)b * D_ + (size_t)g * 8;
    float4 r0 = *(const float4*)(x + obase);
    float4 r1 = *(const float4*)(x + obase + 4);
    float s[8];
#pragma unroll
    for (int o = 0; o < 8; o++) s[o] = sred[o * 132 + b];
    float4 o0 = make_float4(r0.x + s[0], r0.y + s[1], r0.z + s[2], r0.w + s[3]);
    float4 o1 = make_float4(r1.x + s[4], r1.y + s[5], r1.z + s[6], r1.w + s[7]);
    *(float4*)(out + obase)     = o0;
    *(float4*)(out + obase + 4) = o1;
}

// ---------------- launch ----------------

extern "C" void kernel_launch(void* const* d_in, const int* in_sizes, int n_in,
                              void* d_out, int out_size) {
    const float* x  = (const float*)d_in[0];   // (128, 32000) f32
    const float* w  = (const float*)d_in[1];   // (132000, 8, 8) f32
    const int*   bi = (const int*)d_in[2];     // block_in
    const int*   bo = (const int*)d_in[3];     // block_out
    float* out = (float*)d_out;

    pre_kernel<<<4000 + SCAT_CTAS, 256>>>(x, bi, bo);
    main_kernel<<<G_, 128>>>(x, w, out);
}